// round 16
// baseline (speedup 1.0000x reference)
#include <cuda_runtime.h>
#include <cstdint>

// ---------------------------------------------------------------------------
// SimpleESN: h_t = (1-a) h_{t-1} + a * tanh(W_in x_t + W h_{t-1})
//
// R16 = R9's proven clean-pair sync + all post-R9 in-loop wins (R14 core).
//  - producer lane0 stores (h_bits, t+1) as ONE 8B st.cg.v2 pair into
//    g_pair[t&1][row]. Value bits are CLEAN (R15's mantissa tags diverged:
//    2048 steps x 1.8e-6 at SR=0.95 compounds to O(0.1)). Tag is out-of-band
//    in the same 8B word -> atomic together, no cross-address ordering.
//  - consumer thread i stages rows 4i..4i+3 via two ld.cg.v4, retrying
//    (nanosleep(40) backoff) until all 4 tags == t. Detection IS staging:
//    no RED, no spinner, no S1/S3. ONE __syncthreads per step.
//  - h_sm parity double-buffered (stage(t+2) safe after S2(t+1)).
//  - core: L1-resident ELL, conflict-free banks, V[8] hoisted, uniform
//    8 iters, vectorized col loads, u = W_in@x precomputed by one-shot GEMM.
// ---------------------------------------------------------------------------

#define T_STEPS 2048
#define N_RES   4096
#define N_IN    128
#define LEAK    0.3f

#define BLOCKS  128
#define THREADS 1024
#define WARPS   (THREADS / 32)                 // 32
#define ROWS_PER_BLOCK (N_RES / BLOCKS)        // 32 -> 1 row per warp
#define ROW_CAP 512                            // FIXED: 8 iters for all rows
#define GT      16                             // t-values per GEMM block

__device__ uint2          g_tmp[(size_t)N_RES * ROW_CAP];   // build scratch
__device__ float          g_val[(size_t)N_RES * ROW_CAP];
__device__ unsigned short g_col[(size_t)N_RES * ROW_CAP];
__device__ float          g_u[(size_t)T_STEPS * N_RES];     // 33.5 MB: W_in@x_t
__device__ __align__(16) uint2 g_pair[2 * N_RES];           // (h bits, step tag)

__device__ __forceinline__ uint4 ldcg4(const uint4* p) {
    uint4 v;
    asm volatile("ld.global.cg.v4.u32 {%0,%1,%2,%3}, [%4];"
                 : "=r"(v.x), "=r"(v.y), "=r"(v.z), "=r"(v.w) : "l"(p) : "memory");
    return v;
}
__device__ __forceinline__ void stcg2(uint2* p, unsigned a, unsigned b) {
    asm volatile("st.global.cg.v2.u32 [%0], {%1,%2};" :: "l"(p), "r"(a), "r"(b) : "memory");
}

// ---------------------------------------------------------------------------
// One-shot input projection u[t][row] = W_in[row].x_t; block 0 also zeroes
// the pair buffers (tag 0 never matches any want = t >= 1).
// ---------------------------------------------------------------------------
__global__ void __launch_bounds__(1024, 1)
gemm_u_kernel(const float* __restrict__ x, const float* __restrict__ W_in)
{
    __shared__ float4 xs[GT][N_IN / 4];                // 8 KB
    const int tid = threadIdx.x;
    const int t0  = blockIdx.x * GT;

    if (blockIdx.x == 0) {
        #pragma unroll
        for (int i = tid; i < 2 * N_RES; i += 1024) g_pair[i] = make_uint2(0u, 0u);
    }

    if (tid < GT * (N_IN / 4)) {
        int tt = tid >> 5, k4 = tid & 31;
        xs[tt][k4] = __ldg((const float4*)(x + (size_t)(t0 + tt) * N_IN) + k4);
    }
    __syncthreads();

    const float4* w4p = (const float4*)W_in;
    #pragma unroll
    for (int rr = 0; rr < N_RES / 1024; ++rr) {
        const int row = rr * 1024 + tid;
        float acc[GT];
        #pragma unroll
        for (int t = 0; t < GT; ++t) acc[t] = 0.0f;

        #pragma unroll 4
        for (int k4 = 0; k4 < N_IN / 4; ++k4) {
            float4 w = __ldg(w4p + (size_t)row * (N_IN / 4) + k4);
            #pragma unroll
            for (int t = 0; t < GT; ++t) {
                float4 xv = xs[t][k4];
                acc[t] = fmaf(w.x, xv.x, acc[t]);
                acc[t] = fmaf(w.y, xv.y, acc[t]);
                acc[t] = fmaf(w.z, xv.z, acc[t]);
                acc[t] = fmaf(w.w, xv.w, acc[t]);
            }
        }
        #pragma unroll
        for (int t = 0; t < GT; ++t)
            g_u[(size_t)(t0 + t) * N_RES + row] = acc[t];
    }
}

__global__ void __launch_bounds__(THREADS, 1)
esn_kernel(const float* __restrict__ W, float* __restrict__ out)
{
    __shared__ float h_sm[2][N_RES];                   // 32 KB, parity-buffered
    __shared__ int   cnt_sm[WARPS * 32];               // 4 KB: build-phase bins

    const int tid  = threadIdx.x;
    const int wid  = tid >> 5;
    const int lane = tid & 31;
    const int row0 = blockIdx.x * ROWS_PER_BLOCK;
    const int row  = row0 + wid;
    const size_t rowbase = (size_t)row * ROW_CAP;

    // ------------------------------------------------------------------
    // Phase 1: compact row -> g_tmp (ascending cols), count nnz
    // ------------------------------------------------------------------
    int len = 0;
    {
        const float* wrow = W + (size_t)row * N_RES;
        uint2* tmp = g_tmp + rowbase;
        int cnt = 0;
        #pragma unroll 4
        for (int c0 = 0; c0 < N_RES; c0 += 32) {
            float v = wrow[c0 + lane];
            unsigned m = __ballot_sync(0xffffffffu, v != 0.0f);
            if (v != 0.0f) {
                int pos = cnt + __popc(m & ((1u << lane) - 1u));
                if (pos < ROW_CAP)
                    tmp[pos] = make_uint2(__float_as_uint(v), (unsigned)(c0 + lane));
            }
            cnt += __popc(m);
        }
        len = (cnt < ROW_CAP) ? cnt : ROW_CAP;
    }

    // ------------------------------------------------------------------
    // Phase 1.5: bank round-robin reorder, fixed 512 pad, SoA scatter.
    //   slot s (sorted by (m,bank)): s = 64k + 2l + c; vals at s;
    //   cols permuted so lane l's 16 cols are 32B-contiguous: 16l + 2k + c.
    //   pad: val=0, col=0 (broadcast, conflict-free).
    // ------------------------------------------------------------------
    {
        int* cnt = cnt_sm + wid * 32;
        cnt[lane] = 0;
        __syncwarp();

        uint2* tmp = g_tmp + rowbase;
        for (int j = lane; j < len; j += 32) {          // pass A: within-bank idx
            uint2 e = tmp[j];
            int b = (int)(e.y & 31u);
            int m = atomicAdd(&cnt[b], 1);
            tmp[j].y = e.y | ((unsigned)m << 16);
        }
        __syncwarp();

        for (int j = lane; j < ROW_CAP; j += 32) {      // zero-fill all 512
            g_val[rowbase + j] = 0.0f;
            g_col[rowbase + j] = 0;
        }
        __syncwarp();

        for (int j = lane; j < len; j += 32) {          // pass B: rank+scatter
            uint2 e = tmp[j];
            int col = (int)(e.y & 0xFFFu);
            int m   = (int)(e.y >> 16);
            int b   = col & 31;
            int pos = 0;
            #pragma unroll
            for (int b2 = 0; b2 < 32; ++b2) {
                int c = cnt[b2];
                pos += (c < m ? c : m) + (int)((b2 < b) && (c > m));
            }
            int s = (pos & ~63) | ((pos & 31) << 1) | ((pos >> 5) & 1);
            int k = s >> 6, l = (s >> 1) & 31, cc = s & 1;
            g_val[rowbase + s] = __uint_as_float(e.x);
            g_col[rowbase + (l << 4) + (k << 1) + cc] = (unsigned short)col;
        }
    }
    __syncthreads();

    // ------------------------------------------------------------------
    // Hoist loop-invariants: the 16 weight values (cols via 2x LDG.128)
    // ------------------------------------------------------------------
    const float a  = LEAK;
    const float ia = 1.0f - LEAK;
    float2 V[8];
    {
        const float2* vp = (const float2*)(g_val + rowbase);
        #pragma unroll
        for (int k = 0; k < 8; ++k) V[k] = vp[(k << 5) + lane];
    }
    const uint4* cpv = (const uint4*)(g_col + rowbase) + (lane << 1);

    // ------------------------------------------------------------------
    // Phase 2: time recurrence -- no relay; pair tags gate the staging loads
    // ------------------------------------------------------------------
    for (int t = 0; t < T_STEPS; ++t) {
        const int rb = (t + 1) & 1;                    // buffer of h_{t-1}
        float* hs = h_sm[rb];

        // input projection: one dependency-free 4B broadcast load
        float uin = __ldcg(g_u + (size_t)t * N_RES + row);

        // fused detect+stage: thread i retries its rows 4i..4i+3 (two
        // ld.cg.v4 of (h,tag) pairs) until all 4 tags == t
        if (t == 0) {
            *(float4*)(hs + (tid << 2)) = make_float4(0.f, 0.f, 0.f, 0.f);
        } else {
            const uint4* p = (const uint4*)(g_pair + (size_t)rb * N_RES) + (tid << 1);
            const unsigned want = (unsigned)t;         // tag of h_{t-1}
            uint4 A = ldcg4(p);
            uint4 B = ldcg4(p + 1);
            while (((A.y ^ want) | (A.w ^ want) | (B.y ^ want) | (B.w ^ want)) != 0u) {
                __nanosleep(40);
                A = ldcg4(p);
                B = ldcg4(p + 1);
            }
            *(float4*)(hs + (tid << 2)) =
                make_float4(__uint_as_float(A.x), __uint_as_float(A.z),
                            __uint_as_float(B.x), __uint_as_float(B.z));
        }
        __syncthreads();                               // the ONE barrier per step

        // uniform 8-iteration conflict-free gather; vals in regs
        uint4 ca = __ldg(cpv);
        uint4 cb = __ldg(cpv + 1);
        unsigned int cc[8] = {ca.x, ca.y, ca.z, ca.w, cb.x, cb.y, cb.z, cb.w};
        float sum0 = 0.0f, sum1 = 0.0f;
        #pragma unroll
        for (int k = 0; k < 8; ++k) {
            sum0 = fmaf(V[k].x, hs[cc[k] & 0xFFFFu], sum0);
            sum1 = fmaf(V[k].y, hs[cc[k] >> 16],     sum1);
        }

        // butterfly warp reduce
        float sum = sum0 + sum1;
        #pragma unroll
        for (int o = 16; o > 0; o >>= 1)
            sum += __shfl_xor_sync(0xffffffffu, sum, o);

        // publish: CLEAN h value; tag rides in the same 8B pair word
        if (lane == 0) {
            float hn = ia * hs[row] + a * tanhf(sum + uin);
            if (t < T_STEPS - 1)
                stcg2(&g_pair[(size_t)(t & 1) * N_RES + row],
                      __float_as_uint(hn), (unsigned)(t + 1));
            __stcg(out + (size_t)t * N_RES + row, hn);
        }
    }
}

extern "C" void kernel_launch(void* const* d_in, const int* in_sizes, int n_in,
                              void* d_out, int out_size)
{
    const float* x    = (const float*)d_in[0];   // [2048, 128]
    const float* W_in = (const float*)d_in[1];   // [4096, 128]
    const float* W    = (const float*)d_in[2];   // [4096, 4096]
    float* out        = (float*)d_out;           // [2048, 4096]

    gemm_u_kernel<<<T_STEPS / GT, 1024>>>(x, W_in);
    esn_kernel<<<BLOCKS, THREADS>>>(W, out);
}

// round 17
// speedup vs baseline: 1.9382x; 1.9382x over previous
#include <cuda_runtime.h>
#include <cstdint>

// ---------------------------------------------------------------------------
// SimpleESN: h_t = (1-a) h_{t-1} + a * tanh(W_in x_t + W h_{t-1})
//
// R17 = R10 (measured champion, 4549us) + two register-neutral gather trims
// proven correct in R14:
//  - lane's 16 col indices stored 32B-contiguous -> 2x LDG.128 per step
//  - cols stored as BYTE offsets (col<<2 in u16) -> no shift in addressing
// Sync: single counter + one spinner per block + bulk stage (the only scheme
// that survived 8 alternatives: R6/R7/R8/R9/R12/R13/R15/R16 all lost).
// Core: L1-resident per-SM ELL (no L1-invalidating ops ever), bank
// round-robin conflict-free smem gather, V[8] value regs, uniform 8 iters.
// ---------------------------------------------------------------------------

#define T_STEPS 2048
#define N_RES   4096
#define N_IN    128
#define LEAK    0.3f

#define BLOCKS  128
#define THREADS 1024
#define WARPS   (THREADS / 32)                 // 32
#define ROWS_PER_BLOCK (N_RES / BLOCKS)        // 32 -> 1 row per warp
#define ROW_CAP 512                            // FIXED: 8 iters for all rows

__device__ uint2          g_tmp[(size_t)N_RES * ROW_CAP];   // build scratch
__device__ float          g_val[(size_t)N_RES * ROW_CAP];
__device__ unsigned short g_col[(size_t)N_RES * ROW_CAP];
__device__ unsigned int   g_barrier;

__global__ void esn_reset_kernel() { g_barrier = 0u; }

__device__ __forceinline__ unsigned int ld_relaxed_gpu(const unsigned int* p) {
    unsigned int v;
    asm volatile("ld.relaxed.gpu.global.u32 %0, [%1];" : "=r"(v) : "l"(p) : "memory");
    return v;
}
__device__ __forceinline__ void red_release_gpu_add(unsigned int* p, unsigned int v) {
    asm volatile("red.release.gpu.global.add.u32 [%0], %1;" :: "l"(p), "r"(v) : "memory");
}

__global__ void __launch_bounds__(THREADS, 1)
esn_kernel(const float* __restrict__ x,
           const float* __restrict__ W_in,
           const float* __restrict__ W,
           float* __restrict__ out)
{
    __shared__ float h_sm[N_RES];                      // 16 KB
    __shared__ int   cnt_sm[WARPS * 32];               // 4 KB: build-phase bins

    const int tid  = threadIdx.x;
    const int wid  = tid >> 5;
    const int lane = tid & 31;
    const int row0 = blockIdx.x * ROWS_PER_BLOCK;
    const int row  = row0 + wid;
    const size_t rowbase = (size_t)row * ROW_CAP;

    // ------------------------------------------------------------------
    // Phase 1: compact row -> g_tmp (ascending cols), count nnz
    // ------------------------------------------------------------------
    int len = 0;
    {
        const float* wrow = W + (size_t)row * N_RES;
        uint2* tmp = g_tmp + rowbase;
        int cnt = 0;
        #pragma unroll 4
        for (int c0 = 0; c0 < N_RES; c0 += 32) {
            float v = wrow[c0 + lane];
            unsigned m = __ballot_sync(0xffffffffu, v != 0.0f);
            if (v != 0.0f) {
                int pos = cnt + __popc(m & ((1u << lane) - 1u));
                if (pos < ROW_CAP)
                    tmp[pos] = make_uint2(__float_as_uint(v), (unsigned)(c0 + lane));
            }
            cnt += __popc(m);
        }
        len = (cnt < ROW_CAP) ? cnt : ROW_CAP;
    }

    // ------------------------------------------------------------------
    // Phase 1.5: bank round-robin reorder, fixed 512 pad, SoA scatter.
    //   slot s (sorted by (m,bank)): s = 64k + 2l + c; vals stored AT s;
    //   cols stored PERMUTED (lane l's 16 cols contiguous: 16l + 2k + c)
    //   and PRE-SCALED to byte offsets (col<<2).
    //   pad: val=0, col=0 (broadcast, conflict-free).
    // ------------------------------------------------------------------
    {
        int* cnt = cnt_sm + wid * 32;
        cnt[lane] = 0;
        __syncwarp();

        uint2* tmp = g_tmp + rowbase;
        for (int j = lane; j < len; j += 32) {          // pass A: within-bank idx
            uint2 e = tmp[j];
            int b = (int)(e.y & 31u);
            int m = atomicAdd(&cnt[b], 1);
            tmp[j].y = e.y | ((unsigned)m << 16);
        }
        __syncwarp();

        for (int j = lane; j < ROW_CAP; j += 32) {      // zero-fill all 512
            g_val[rowbase + j] = 0.0f;
            g_col[rowbase + j] = 0;
        }
        __syncwarp();

        for (int j = lane; j < len; j += 32) {          // pass B: rank+scatter
            uint2 e = tmp[j];
            int col = (int)(e.y & 0xFFFu);
            int m   = (int)(e.y >> 16);
            int b   = col & 31;
            int pos = 0;
            #pragma unroll
            for (int b2 = 0; b2 < 32; ++b2) {
                int c = cnt[b2];
                pos += (c < m ? c : m) + (int)((b2 < b) && (c > m));
            }
            int s = (pos & ~63) | ((pos & 31) << 1) | ((pos >> 5) & 1);
            int k = s >> 6, l = (s >> 1) & 31, cc = s & 1;
            g_val[rowbase + s] = __uint_as_float(e.x);
            g_col[rowbase + (l << 4) + (k << 1) + cc] = (unsigned short)(col << 2);
        }
    }
    __syncthreads();

    // ------------------------------------------------------------------
    // Hoist loop-invariants: W_in row + the 16 weight values
    // ------------------------------------------------------------------
    const float a  = LEAK;
    const float ia = 1.0f - LEAK;
    const float4 w4 = __ldg((const float4*)(W_in + (size_t)row * N_IN) + lane);

    float2 V[8];
    {
        const float2* vp = (const float2*)(g_val + rowbase);
        #pragma unroll
        for (int k = 0; k < 8; ++k) V[k] = vp[(k << 5) + lane];
    }
    const uint4* cpv = (const uint4*)(g_col + rowbase) + (lane << 1);
    const char* hbase = (const char*)h_sm;

    // ------------------------------------------------------------------
    // Phase 2: time recurrence (sync scheme = R10 exactly)
    // ------------------------------------------------------------------
    for (int t = 0; t < T_STEPS; ++t) {
        // h-independent dense part (overlaps the wait below)
        float4 x4 = __ldg((const float4*)(x + (size_t)t * N_IN) + lane);
        float sum0 = w4.x * x4.x + w4.y * x4.y;
        float sum1 = w4.z * x4.z + w4.w * x4.w;

        // global gate: single spinner on the single counter
        if (t > 0) {
            if (tid == 0) {
                const unsigned int want = (unsigned int)t * BLOCKS;
                while (ld_relaxed_gpu(&g_barrier) < want) { }
            }
            __syncthreads();   // S1
        }

        // bulk stage h_{t-1} into smem (L2-direct, always coherent)
        if (t == 0) {
            for (int i = tid; i < N_RES; i += THREADS) h_sm[i] = 0.0f;
        } else {
            const float4* hprev = (const float4*)(out + (size_t)(t - 1) * N_RES);
            float4 v = __ldcg(hprev + tid);
            *(float4*)(h_sm + tid * 4) = v;
        }
        __syncthreads();       // S2

        // uniform 8-iteration conflict-free gather; vals in regs, cols via
        // two LDG.128, indices are pre-scaled byte offsets
        uint4 ca = __ldg(cpv);
        uint4 cb = __ldg(cpv + 1);
        unsigned int cc[8] = {ca.x, ca.y, ca.z, ca.w, cb.x, cb.y, cb.z, cb.w};
        #pragma unroll
        for (int k = 0; k < 8; ++k) {
            sum0 = fmaf(V[k].x, *(const float*)(hbase + (cc[k] & 0xFFFFu)), sum0);
            sum1 = fmaf(V[k].y, *(const float*)(hbase + (cc[k] >> 16)),     sum1);
        }

        // butterfly warp reduce
        float sum = sum0 + sum1;
        #pragma unroll
        for (int o = 16; o > 0; o >>= 1)
            sum += __shfl_xor_sync(0xffffffffu, sum, o);

        if (lane == 0) {
            float hn = ia * h_sm[row] + a * tanhf(sum);
            __stcg(out + (size_t)t * N_RES + row, hn);
        }

        if (t < T_STEPS - 1) {
            __syncthreads();                 // S3: all rows of this block in L2
            if (tid == 0) red_release_gpu_add(&g_barrier, 1u);
        }
    }
}

extern "C" void kernel_launch(void* const* d_in, const int* in_sizes, int n_in,
                              void* d_out, int out_size)
{
    const float* x    = (const float*)d_in[0];   // [2048, 128]
    const float* W_in = (const float*)d_in[1];   // [4096, 128]
    const float* W    = (const float*)d_in[2];   // [4096, 4096]
    float* out        = (float*)d_out;           // [2048, 4096]

    esn_reset_kernel<<<1, 1>>>();
    esn_kernel<<<BLOCKS, THREADS>>>(x, W_in, W, out);
}